// round 2
// baseline (speedup 1.0000x reference)
#include <cuda_runtime.h>
#include <math.h>

// Problem constants
// B=1, N=256, Q=K=256, C=128, H=4, C_HID=32
#define NROW   65536      // B*N*Q rows
#define CDIM   128        // channel dim == H*C_HID
#define NSEQ   256
#define NHEAD  4
#define CHID   32

// Scratch (allocation-free rule: __device__ globals)
__device__ float g_qbuf[(size_t)NROW * CDIM];
__device__ float g_kbuf[(size_t)NROW * CDIM];
__device__ float g_vbuf[(size_t)NROW * CDIM];
__device__ float g_gbuf[(size_t)NROW * CDIM];
__device__ float g_obuf[(size_t)NROW * CDIM];

// ---------------------------------------------------------------------------
// GEMM: Y[M,128] = epilogue( X[M,128] @ W[128,128] )
// op: 0 = none, 1 = scale by alpha, 2 = sigmoid
// Tile: BM=64, BN=128, BK=64 (two K tiles). 256 threads, 8x4 per-thread block.
// smem = 32KB (W tile) + 16KB (X tile) = 48KB static.
// ---------------------------------------------------------------------------
__global__ void __launch_bounds__(256) gemm128_kernel(
    const float* __restrict__ X, const float* __restrict__ W,
    float* __restrict__ Y, int op, float alpha)
{
    __shared__ float sW[64 * 128];
    __shared__ float sX[64 * 64];

    const int tid = threadIdx.x;
    const int m0  = blockIdx.x * 64;
    const int tx  = tid & 31;    // 32 col-groups of 4
    const int ty  = tid >> 5;    // 8 row-groups of 8

    float acc[8][4];
#pragma unroll
    for (int r = 0; r < 8; r++)
#pragma unroll
        for (int c = 0; c < 4; c++) acc[r][c] = 0.f;

    for (int k0 = 0; k0 < 128; k0 += 64) {
        // W tile: rows [k0,k0+64) x 128 cols, contiguous
        const float4* W4 = (const float4*)(W + (size_t)k0 * 128);
        float4* sW4 = (float4*)sW;
        for (int i = tid; i < 64 * 32; i += 256) sW4[i] = W4[i];
        // X tile: 64 rows x cols [k0,k0+64)
        float4* sX4 = (float4*)sX;
        for (int i = tid; i < 64 * 16; i += 256) {
            int row = i >> 4, cc = i & 15;
            sX4[row * 16 + cc] =
                *(const float4*)(X + ((size_t)(m0 + row)) * 128 + k0 + cc * 4);
        }
        __syncthreads();

#pragma unroll 8
        for (int k = 0; k < 64; k++) {
            float4 w4 = *(const float4*)&sW[k * 128 + tx * 4];  // conflict-free
#pragma unroll
            for (int r = 0; r < 8; r++) {
                float xv = sX[(ty * 8 + r) * 64 + k];           // warp broadcast
                acc[r][0] = fmaf(xv, w4.x, acc[r][0]);
                acc[r][1] = fmaf(xv, w4.y, acc[r][1]);
                acc[r][2] = fmaf(xv, w4.z, acc[r][2]);
                acc[r][3] = fmaf(xv, w4.w, acc[r][3]);
            }
        }
        __syncthreads();
    }

#pragma unroll
    for (int r = 0; r < 8; r++) {
        float4 o;
        o.x = acc[r][0]; o.y = acc[r][1]; o.z = acc[r][2]; o.w = acc[r][3];
        if (op == 1) {
            o.x *= alpha; o.y *= alpha; o.z *= alpha; o.w *= alpha;
        } else if (op == 2) {
            o.x = 1.f / (1.f + __expf(-o.x));
            o.y = 1.f / (1.f + __expf(-o.y));
            o.z = 1.f / (1.f + __expf(-o.z));
            o.w = 1.f / (1.f + __expf(-o.w));
        }
        *(float4*)(Y + ((size_t)(m0 + ty * 8 + r)) * 128 + tx * 4) = o;
    }
}

// ---------------------------------------------------------------------------
// Attention: one CTA per (n, h). 256 threads, one thread per q row.
// Online softmax over K=256 (two smem tiles of 128 K/V rows).
// out[r, h*32+c] = (softmax(q·k + tri + mb) @ v)[c] * gate[r, h*32+c]
// smem: K tile 16KB + V tile 16KB + mask_bias 1KB = 33KB static.
// ---------------------------------------------------------------------------
__global__ void __launch_bounds__(256) attn_kernel(
    const float* __restrict__ qb, const float* __restrict__ kb,
    const float* __restrict__ vb, const float* __restrict__ gb,
    const float* __restrict__ tri, const float* __restrict__ mb,
    float* __restrict__ ob)
{
    __shared__ float ks[128 * 32];
    __shared__ float vs[128 * 32];
    __shared__ float mbs[256];

    const int n   = blockIdx.x;
    const int h   = blockIdx.y;
    const int tid = threadIdx.x;
    const int qi  = tid;

    mbs[tid] = mb[(size_t)n * 256 + tid];

    const size_t qbase = ((size_t)(n * 256 + qi)) * 128 + h * 32;
    float q[32];
#pragma unroll
    for (int c = 0; c < 32; c += 4) {
        float4 t = *(const float4*)&qb[qbase + c];
        q[c] = t.x; q[c + 1] = t.y; q[c + 2] = t.z; q[c + 3] = t.w;
    }
    const float* trow = tri + ((size_t)(h * 256 + qi)) * 256;

    float m = -INFINITY, l = 0.f;
    float acc[32];
#pragma unroll
    for (int c = 0; c < 32; c++) acc[c] = 0.f;

    for (int jt = 0; jt < 256; jt += 128) {
        __syncthreads();
        // cooperative load of K/V tile: rows [jt, jt+128), 32 cols of head h
        for (int i = tid; i < 128 * 32; i += 256) {
            int row = i >> 5, c = i & 31;
            size_t src = ((size_t)(n * 256 + jt + row)) * 128 + h * 32 + c;
            ks[i] = kb[src];
            vs[i] = vb[src];
        }
        __syncthreads();

        for (int jr = 0; jr < 128; jr++) {
            const float4* k4 = (const float4*)&ks[jr * 32];
            float s = 0.f;
#pragma unroll
            for (int c = 0; c < 8; c++) {
                float4 kk = k4[c];
                s = fmaf(q[4 * c + 0], kk.x, s);
                s = fmaf(q[4 * c + 1], kk.y, s);
                s = fmaf(q[4 * c + 2], kk.z, s);
                s = fmaf(q[4 * c + 3], kk.w, s);
            }
            int j = jt + jr;
            s += trow[j] + mbs[j];

            if (s > m) {
                float corr = __expf(m - s);   // expf(-inf)=0 handles first iter
                m = s;
                l *= corr;
#pragma unroll
                for (int c = 0; c < 32; c++) acc[c] *= corr;
            }
            float p = __expf(s - m);
            l += p;
            const float4* v4 = (const float4*)&vs[jr * 32];
#pragma unroll
            for (int c = 0; c < 8; c++) {
                float4 vv = v4[c];
                acc[4 * c + 0] = fmaf(p, vv.x, acc[4 * c + 0]);
                acc[4 * c + 1] = fmaf(p, vv.y, acc[4 * c + 1]);
                acc[4 * c + 2] = fmaf(p, vv.z, acc[4 * c + 2]);
                acc[4 * c + 3] = fmaf(p, vv.w, acc[4 * c + 3]);
            }
        }
    }

    const float inv = 1.f / l;
#pragma unroll
    for (int c = 0; c < 32; c += 4) {
        float4 gg = *(const float4*)&gb[qbase + c];
        float4 o;
        o.x = acc[c + 0] * inv * gg.x;
        o.y = acc[c + 1] * inv * gg.y;
        o.z = acc[c + 2] * inv * gg.z;
        o.w = acc[c + 3] * inv * gg.w;
        *(float4*)&ob[qbase + c] = o;
    }
}

// ---------------------------------------------------------------------------
// Launch
// Inputs (metadata order): q_x, kv_x, tri_bias, mask_bias, mask(unused),
//                          Wq, Wk, Wv, Wg, Wo
// ---------------------------------------------------------------------------
extern "C" void kernel_launch(void* const* d_in, const int* in_sizes, int n_in,
                              void* d_out, int out_size)
{
    const float* q_x  = (const float*)d_in[0];
    const float* kv_x = (const float*)d_in[1];
    const float* tri  = (const float*)d_in[2];
    const float* mbp  = (const float*)d_in[3];
    const float* Wq   = (const float*)d_in[5];
    const float* Wk   = (const float*)d_in[6];
    const float* Wv   = (const float*)d_in[7];
    const float* Wg   = (const float*)d_in[8];
    const float* Wo   = (const float*)d_in[9];
    float* out = (float*)d_out;

    float *qb, *kb, *vb, *gb, *ob;
    cudaGetSymbolAddress((void**)&qb, g_qbuf);
    cudaGetSymbolAddress((void**)&kb, g_kbuf);
    cudaGetSymbolAddress((void**)&vb, g_vbuf);
    cudaGetSymbolAddress((void**)&gb, g_gbuf);
    cudaGetSymbolAddress((void**)&ob, g_obuf);

    const int grid = NROW / 64;  // 1024
    const float qscale = 0.17677669529663687f;  // 1/sqrt(32)

    gemm128_kernel<<<grid, 256>>>(q_x,  Wq, qb, 1, qscale);
    gemm128_kernel<<<grid, 256>>>(kv_x, Wk, kb, 0, 1.f);
    gemm128_kernel<<<grid, 256>>>(kv_x, Wv, vb, 0, 1.f);
    gemm128_kernel<<<grid, 256>>>(q_x,  Wg, gb, 2, 1.f);

    attn_kernel<<<dim3(NSEQ, NHEAD), 256>>>(qb, kb, vb, gb, tri, mbp, ob);

    gemm128_kernel<<<grid, 256>>>(ob, Wo, out, 0, 1.f);
}

// round 3
// speedup vs baseline: 1.3504x; 1.3504x over previous
#include <cuda_runtime.h>
#include <math.h>

// Problem constants: B=1, N=256, Q=K=256, C=128, H=4, C_HID=32
#define NROW   65536
#define CDIM   128
#define NSEQ   256
#define NHEAD  4
#define CHID   32

// Scratch (allocation-free rule: __device__ globals)
__device__ float g_qbuf[(size_t)NROW * CDIM];
__device__ float g_kbuf[(size_t)NROW * CDIM];
__device__ float g_vbuf[(size_t)NROW * CDIM];
__device__ float g_gbuf[(size_t)NROW * CDIM];
__device__ float g_obuf[(size_t)NROW * CDIM];

// ---------------------------------------------------------------------------
// Packed f32x2 helpers (Blackwell dual-fp32 pipe; ptxas never emits these)
// ---------------------------------------------------------------------------
typedef unsigned long long ull;

__device__ __forceinline__ ull pk2(float lo, float hi) {
    ull r;
    asm("mov.b64 %0, {%1, %2};" : "=l"(r) : "f"(lo), "f"(hi));
    return r;
}
__device__ __forceinline__ void upk2(ull v, float& lo, float& hi) {
    asm("mov.b64 {%0, %1}, %2;" : "=f"(lo), "=f"(hi) : "l"(v));
}
__device__ __forceinline__ ull ffma2(ull a, ull b, ull c) {
    ull d;
    asm("fma.rn.f32x2 %0, %1, %2, %3;" : "=l"(d) : "l"(a), "l"(b), "l"(c));
    return d;
}
__device__ __forceinline__ ull fmul2(ull a, ull b) {
    ull d;
    asm("mul.rn.f32x2 %0, %1, %2;" : "=l"(d) : "l"(a), "l"(b));
    return d;
}

union F4U2 {          // reinterpret a float4 register quad as two packed pairs
    float4 f4;
    ull    u2[2];
};

// ---------------------------------------------------------------------------
// GEMM: Y[M,128] = epilogue( X[M,128] @ W[128,128] ), f32x2 mainloop.
// Tile BM=64, BN=128, BK=32. 256 threads, 8 rows x 4 cols per thread.
// X is stored DUPLICATED in smem as (v,v) pairs -> broadcast operand needs no
// packing; W's float4 load gives the two column pairs for free.
// smem: sW 32x128 f32 (16KB) + sXd 64x32 f32x2 (16KB) = 32KB.
// ---------------------------------------------------------------------------
__global__ void __launch_bounds__(256) gemm128_kernel(
    const float* __restrict__ X, const float* __restrict__ W,
    float* __restrict__ Y, int op, float alpha)
{
    __shared__ float sW[32 * 128];
    __shared__ ull   sXd[64 * 32];

    const int tid = threadIdx.x;
    const int m0  = blockIdx.x * 64;
    const int tx  = tid & 31;    // col group of 4 (2 pairs)
    const int ty  = tid >> 5;    // row group of 8

    ull acc[8][2];
#pragma unroll
    for (int r = 0; r < 8; r++) { acc[r][0] = 0ull; acc[r][1] = 0ull; }

    for (int k0 = 0; k0 < 128; k0 += 32) {
        // W tile: rows [k0,k0+32) x 128 cols (contiguous block)
        {
            const float4* W4 = (const float4*)(W + (size_t)k0 * 128);
            float4* sW4 = (float4*)sW;
#pragma unroll
            for (int i = 0; i < 4; i++) sW4[tid + 256 * i] = W4[tid + 256 * i];
        }
        // X tile: 64 rows x 32 k, duplicated pairs
        {
#pragma unroll
            for (int i = 0; i < 2; i++) {
                int idx = tid + 256 * i;            // over 512 float4 slots
                int row = idx >> 3, kc = idx & 7;   // kc: group of 4 k
                float4 x = *(const float4*)(X + ((size_t)(m0 + row)) * 128 + k0 + kc * 4);
                ull* dst = &sXd[row * 32 + kc * 4];
                dst[0] = pk2(x.x, x.x);
                dst[1] = pk2(x.y, x.y);
                dst[2] = pk2(x.z, x.z);
                dst[3] = pk2(x.w, x.w);
            }
        }
        __syncthreads();

        const ull* xrow = &sXd[(ty * 8) * 32];
#pragma unroll 8
        for (int k = 0; k < 32; k++) {
            F4U2 w; w.f4 = *(const float4*)&sW[k * 128 + tx * 4];
#pragma unroll
            for (int r = 0; r < 8; r++) {
                ull xv2 = xrow[r * 32 + k];         // warp-uniform broadcast
                acc[r][0] = ffma2(xv2, w.u2[0], acc[r][0]);
                acc[r][1] = ffma2(xv2, w.u2[1], acc[r][1]);
            }
        }
        __syncthreads();
    }

#pragma unroll
    for (int r = 0; r < 8; r++) {
        float4 o;
        upk2(acc[r][0], o.x, o.y);
        upk2(acc[r][1], o.z, o.w);
        if (op == 1) {
            o.x *= alpha; o.y *= alpha; o.z *= alpha; o.w *= alpha;
        } else if (op == 2) {
            o.x = 1.f / (1.f + __expf(-o.x));
            o.y = 1.f / (1.f + __expf(-o.y));
            o.z = 1.f / (1.f + __expf(-o.z));
            o.w = 1.f / (1.f + __expf(-o.w));
        }
        *(float4*)(Y + ((size_t)(m0 + ty * 8 + r)) * 128 + tx * 4) = o;
    }
}

// ---------------------------------------------------------------------------
// Attention: one CTA per (n, h), one thread per q row. Chunked online softmax
// (chunk=8: one max/rescale per 8 keys) with f32x2 dot products / accumulate.
// ---------------------------------------------------------------------------
__global__ void __launch_bounds__(256) attn_kernel(
    const float* __restrict__ qb, const float* __restrict__ kb,
    const float* __restrict__ vb, const float* __restrict__ gb,
    const float* __restrict__ tri, const float* __restrict__ mb,
    float* __restrict__ ob)
{
    __shared__ float ks[128 * 32];
    __shared__ float vs[128 * 32];
    __shared__ float mbs[256];

    const int n   = blockIdx.x;
    const int h   = blockIdx.y;
    const int tid = threadIdx.x;
    const int qi  = tid;

    mbs[tid] = mb[(size_t)n * 256 + tid];

    const size_t qbase = ((size_t)(n * 256 + qi)) * 128 + h * 32;
    ull q2[16];
#pragma unroll
    for (int c = 0; c < 8; c++) {
        F4U2 t; t.f4 = *(const float4*)&qb[qbase + c * 4];
        q2[2 * c]     = t.u2[0];
        q2[2 * c + 1] = t.u2[1];
    }
    const float* trow = tri + ((size_t)(h * 256 + qi)) * 256;

    float m = -INFINITY, l = 0.f;
    ull acc[16];
#pragma unroll
    for (int c = 0; c < 16; c++) acc[c] = 0ull;

    for (int jt = 0; jt < 256; jt += 128) {
        __syncthreads();
        {   // cooperative tile load: 128 rows x 32 cols of head h, float4
            const float4* kb4 = (const float4*)(kb + ((size_t)(n * 256 + jt)) * 128 + h * 32);
            const float4* vb4 = (const float4*)(vb + ((size_t)(n * 256 + jt)) * 128 + h * 32);
            float4* ks4 = (float4*)ks;
            float4* vs4 = (float4*)vs;
#pragma unroll
            for (int i = 0; i < 4; i++) {
                int idx = tid + 256 * i;           // 1024 float4 slots
                int row = idx >> 3, c4 = idx & 7;  // src row stride = 32 float4
                ks4[idx] = kb4[row * 32 + c4];
                vs4[idx] = vb4[row * 32 + c4];
            }
        }
        __syncthreads();

        for (int jc = 0; jc < 128; jc += 8) {
            // ---- scores for 8 keys ----
            float s[8];
            float4 tb0 = *(const float4*)&trow[jt + jc];
            float4 tb1 = *(const float4*)&trow[jt + jc + 4];
            float tb[8] = {tb0.x, tb0.y, tb0.z, tb0.w, tb1.x, tb1.y, tb1.z, tb1.w};
#pragma unroll
            for (int u = 0; u < 8; u++) {
                const float4* kr = (const float4*)&ks[(jc + u) * 32];
                ull s2 = 0ull;
#pragma unroll
                for (int c = 0; c < 8; c++) {
                    F4U2 kk; kk.f4 = kr[c];
                    s2 = ffma2(q2[2 * c],     kk.u2[0], s2);
                    s2 = ffma2(q2[2 * c + 1], kk.u2[1], s2);
                }
                float lo, hi; upk2(s2, lo, hi);
                s[u] = lo + hi + tb[u] + mbs[jt + jc + u];
            }
            // ---- chunk max + single rescale ----
            float cmax = s[0];
#pragma unroll
            for (int u = 1; u < 8; u++) cmax = fmaxf(cmax, s[u]);
            float mnew = fmaxf(m, cmax);
            float corr = __expf(m - mnew);   // first chunk: exp(-inf)=0
            m = mnew;
            l *= corr;
            ull c2 = pk2(corr, corr);
#pragma unroll
            for (int c = 0; c < 16; c++) acc[c] = fmul2(acc[c], c2);
            // ---- accumulate 8 keys ----
#pragma unroll
            for (int u = 0; u < 8; u++) {
                float p = __expf(s[u] - m);
                l += p;
                ull p2 = pk2(p, p);
                const float4* vr = (const float4*)&vs[(jc + u) * 32];
#pragma unroll
                for (int c = 0; c < 8; c++) {
                    F4U2 vv; vv.f4 = vr[c];
                    acc[2 * c]     = ffma2(p2, vv.u2[0], acc[2 * c]);
                    acc[2 * c + 1] = ffma2(p2, vv.u2[1], acc[2 * c + 1]);
                }
            }
        }
    }

    const float inv = 1.f / l;
#pragma unroll
    for (int c = 0; c < 8; c++) {
        float4 gg = *(const float4*)&gb[qbase + c * 4];
        float a0, a1, a2, a3;
        upk2(acc[2 * c],     a0, a1);
        upk2(acc[2 * c + 1], a2, a3);
        float4 o;
        o.x = a0 * inv * gg.x;
        o.y = a1 * inv * gg.y;
        o.z = a2 * inv * gg.z;
        o.w = a3 * inv * gg.w;
        *(float4*)&ob[qbase + c * 4] = o;
    }
}

// ---------------------------------------------------------------------------
// Launch. Inputs: q_x, kv_x, tri_bias, mask_bias, mask(unused), Wq,Wk,Wv,Wg,Wo
// ---------------------------------------------------------------------------
extern "C" void kernel_launch(void* const* d_in, const int* in_sizes, int n_in,
                              void* d_out, int out_size)
{
    const float* q_x  = (const float*)d_in[0];
    const float* kv_x = (const float*)d_in[1];
    const float* tri  = (const float*)d_in[2];
    const float* mbp  = (const float*)d_in[3];
    const float* Wq   = (const float*)d_in[5];
    const float* Wk   = (const float*)d_in[6];
    const float* Wv   = (const float*)d_in[7];
    const float* Wg   = (const float*)d_in[8];
    const float* Wo   = (const float*)d_in[9];
    float* out = (float*)d_out;

    float *qb, *kb, *vb, *gb, *ob;
    cudaGetSymbolAddress((void**)&qb, g_qbuf);
    cudaGetSymbolAddress((void**)&kb, g_kbuf);
    cudaGetSymbolAddress((void**)&vb, g_vbuf);
    cudaGetSymbolAddress((void**)&gb, g_gbuf);
    cudaGetSymbolAddress((void**)&ob, g_obuf);

    const int grid = NROW / 64;  // 1024
    const float qscale = 0.17677669529663687f;  // 1/sqrt(32)

    gemm128_kernel<<<grid, 256>>>(q_x,  Wq, qb, 1, qscale);
    gemm128_kernel<<<grid, 256>>>(kv_x, Wk, kb, 0, 1.f);
    gemm128_kernel<<<grid, 256>>>(kv_x, Wv, vb, 0, 1.f);
    gemm128_kernel<<<grid, 256>>>(q_x,  Wg, gb, 2, 1.f);

    attn_kernel<<<dim3(NSEQ, NHEAD), 256>>>(qb, kb, vb, gb, tri, mbp, ob);

    gemm128_kernel<<<grid, 256>>>(ob, Wo, out, 0, 1.f);
}